// round 16
// baseline (speedup 1.0000x reference)
#include <cuda_runtime.h>
#include <math.h>
#include <float.h>

#define NMAX 20000
#define EMAX 320000
#define H 128
#define T 4
#define FIN 32
#define FULLM 0xffffffffu
#define NB 132     // resident blocks for fused setup
#define STH 512    // k_setup threads per block

typedef unsigned long long ull;

// ---------------- f32x2 packed helpers ----------------
__device__ __forceinline__ ull packf2(float lo, float hi) {
    ull r;
    asm("mov.b64 %0, {%1, %2};" : "=l"(r) : "r"(__float_as_uint(lo)), "r"(__float_as_uint(hi)));
    return r;
}
__device__ __forceinline__ ull dupf2(float w) {
    ull r;
    asm("mov.b64 %0, {%1, %1};" : "=l"(r) : "r"(__float_as_uint(w)));
    return r;
}
__device__ __forceinline__ void unpackf2(ull v, float& lo, float& hi) {
    unsigned int a, b;
    asm("mov.b64 {%0, %1}, %2;" : "=r"(a), "=r"(b) : "l"(v));
    lo = __uint_as_float(a); hi = __uint_as_float(b);
}
__device__ __forceinline__ ull fma2(ull a, ull b, ull c) {
    ull d;
    asm("fma.rn.f32x2 %0, %1, %2, %3;" : "=l"(d) : "l"(a), "l"(b), "l"(c));
    return d;
}
__device__ __forceinline__ ull add2(ull a, ull b) {
    ull d;
    asm("add.rn.f32x2 %0, %1, %2;" : "=l"(d) : "l"(a), "l"(b));
    return d;
}

// ---------------- device scratch ----------------
__device__ float g_avg_log;
__device__ float g_enc[5 * FIN];
__device__ int   g_deg[NMAX];
__device__ int   g_off[NMAX + 1];
__device__ int   g_fill[NMAX];
__device__ int   g_csr[EMAX];                 // packed: (src*H) | (bond<<27)
__device__ int   g_part[NB];
__device__ float g_a0[(size_t)NMAX * H];
__device__ float g_p [(size_t)NMAX * H];
__device__ float g_agg[(size_t)NMAX * T * 5 * FIN];
__device__ unsigned int g_bar;
__device__ unsigned int g_done;

// ---------------- fused setup: zero + hist + PRE + SCALARS + scan + scatter ----------------
__device__ __forceinline__ void grid_bar(unsigned target) {
    __syncthreads();
    if (threadIdx.x == 0) {
        __threadfence();
        atomicAdd(&g_bar, 1u);
        while (*((volatile unsigned int*)&g_bar) < target) { }
        __threadfence();
    }
    __syncthreads();
}

__global__ void __launch_bounds__(STH) k_setup(
    const int* __restrict__ dst, const int* __restrict__ src,
    const int* __restrict__ bond,
    const float* __restrict__ atom_x,
    const float* __restrict__ pre_w1, const float* __restrict__ pre_b1,
    const int* __restrict__ mol_deg,
    const float* __restrict__ bond_emb,
    const float* __restrict__ enc_w, const float* __restrict__ enc_b,
    int N, int E) {
    const int tid = threadIdx.x, b = blockIdx.x;
    const int gsz = NB * STH;
    const int gid = b * STH + tid;
    __shared__ int sh[STH];
    __shared__ float sf[256], sf2[256];
    __shared__ int s_poff;

    // P0: zero degree counters
    for (int i = gid; i < N; i += gsz) __stcg(&g_deg[i], 0);
    grid_bar(NB * 1);

    // P1: degree histogram
    for (int e = gid; e < E; e += gsz) atomicAdd(&g_deg[__ldg(&dst[e])], 1);

    // SCALARS (block 1, independent of hist): avg_log + bond-encode table
    if (b == 1 && tid < 256) {
        float num = 0.f, den = 0.f;
        if (tid < 128) {
            float d = (float)mol_deg[tid];
            num = logf((float)tid + 1.0f) * d;
            den = d;
        }
        sf[tid] = num; sf2[tid] = den;
        __syncwarp();
    }
    if (b == 1) {
        __syncthreads();
        if (tid < 128) { sf[tid] += sf[tid + 128]; sf2[tid] += sf2[tid + 128]; }
        __syncthreads();
        if (tid < 64) { sf[tid] += sf[tid + 64]; sf2[tid] += sf2[tid + 64]; }
        __syncthreads();
        if (tid < 32) {
            float s = sf[tid] + sf[tid + 32];
            float d = sf2[tid] + sf2[tid + 32];
#pragma unroll
            for (int off = 16; off > 0; off >>= 1) {
                s += __shfl_down_sync(FULLM, s, off);
                d += __shfl_down_sync(FULLM, d, off);
            }
            if (tid == 0) g_avg_log = s / d;
        }
        if (tid < 5 * FIN) {
            int bb = tid >> 5, g = tid & 31;
            float a = enc_b[g];
            for (int k = 0; k < H; k++) a += bond_emb[bb * H + k] * enc_w[k * FIN + g];
            g_enc[bb * FIN + g] = a;
        }
        __syncthreads();
    }

    // PRE (independent of hist): A0 = b1 + W1a.x, P = W1b.x
    {
        const int l = tid & 31;
        const int w = tid >> 5;
        const int t = w & 3;
        float w1a[FIN], w1b[FIN];
#pragma unroll
        for (int f = 0; f < FIN; f++) w1a[f] = pre_w1[(t * 96 + f) * FIN + l];
#pragma unroll
        for (int f = 0; f < FIN; f++) w1b[f] = pre_w1[(t * 96 + 32 + f) * FIN + l];
        const float b1 = pre_b1[t * FIN + l];
        for (int n = b * 8 + (w >> 2) * 2; n < N; n += NB * 8) {
            const bool has2 = (n + 1) < N;
            const int n2 = has2 ? n + 1 : n;
            float x0 = atom_x[n * H + t * FIN + l];
            float x1 = atom_x[n2 * H + t * FIN + l];
            float a00 = b1, p0 = 0.f, a01 = b1, p1 = 0.f;
#pragma unroll
            for (int f = 0; f < FIN; f++) {
                float xf0 = __shfl_sync(FULLM, x0, f);
                float xf1 = __shfl_sync(FULLM, x1, f);
                a00 += xf0 * w1a[f];
                p0  += xf0 * w1b[f];
                a01 += xf1 * w1a[f];
                p1  += xf1 * w1b[f];
            }
            g_a0[n * H + t * FIN + l] = a00;
            g_p [n * H + t * FIN + l] = p0;
            if (has2) {
                g_a0[n2 * H + t * FIN + l] = a01;
                g_p [n2 * H + t * FIN + l] = p1;
            }
        }
    }
    grid_bar(NB * 2);

    // P2: per-block chunk scan
    const int chunk = (N + NB - 1) / NB;
    const int i = b * chunk + tid;
    int v = (tid < chunk && i < N) ? __ldcg(&g_deg[i]) : 0;
    sh[tid] = v;
    __syncthreads();
    for (int off = 1; off < STH; off <<= 1) {
        int tv = (tid >= off) ? sh[tid - off] : 0;
        __syncthreads();
        sh[tid] += tv;
        __syncthreads();
    }
    int local_excl = sh[tid] - v;
    if (tid == STH - 1) __stcg(&g_part[b], sh[STH - 1]);
    grid_bar(NB * 3);

    // P3: every block computes its own prefix over g_part[<b]
    if (tid < 32) {
        int s = 0;
        for (int ii = tid; ii < b; ii += 32) s += __ldcg(&g_part[ii]);
#pragma unroll
        for (int off = 16; off > 0; off >>= 1) s += __shfl_down_sync(FULLM, s, off);
        if (tid == 0) s_poff = s;
    }
    if (b == 0 && tid == 33) __stcg(&g_off[N], E);
    __syncthreads();
    {
        int po = s_poff;
        if (tid < chunk && i < N) {
            int vv = local_excl + po;
            __stcg(&g_off[i], vv);
            __stcg(&g_fill[i], vv);
        }
    }
    grid_bar(NB * 4);

    // P5: scatter edges into CSR (src pre-multiplied by H)
    for (int e = gid; e < E; e += gsz) {
        int d = __ldg(&dst[e]);
        int p = atomicAdd(&g_fill[d], 1);
        __stcg(&g_csr[p], (__ldg(&src[e]) * H) | (__ldg(&bond[e]) << 27));
    }

    __syncthreads();
    if (tid == 0) {
        if (atomicAdd(&g_done, 1u) == NB - 1) {
            atomicExch(&g_bar, 0u);
            atomicExch(&g_done, 0u);
        }
    }
}

// ---------------- dummy (shifts k_tail to ncu-captured launch index 3) ----------------
__global__ void k_dummy() {}

// ---------------- edge loop: dual-node, PAIR-PACKED f32x2 dot ----------------
__device__ __forceinline__ void dot_pair(const float2* buf, const float* w2, float b2,
                                         float& m0, float& m1) {
    ull acc = 0ull;
#pragma unroll
    for (int j = 0; j < 16; j++) {
        ulonglong2 v = *(const ulonglong2*)&buf[2 * j];
        acc = fma2(v.x, dupf2(w2[2 * j]), acc);
        acc = fma2(v.y, dupf2(w2[2 * j + 1]), acc);
    }
    unpackf2(acc, m0, m1);
    m0 += b2; m1 += b2;
}

__global__ void __launch_bounds__(128, 6) k_agg(
    const float* __restrict__ pre_w1,
    const float* __restrict__ pre_w2, const float* __restrict__ pre_b2, int N) {
    const int l = threadIdx.x & 31;
    const int t = threadIdx.x >> 5;
    __shared__ __align__(16) float2 rs2[4][2][2][32];  // [warp][parity][stream][feature]
    __shared__ float evtab[4][5][32];

    float w2v[FIN];
#pragma unroll
    for (int j = 0; j < FIN; j++) w2v[j] = pre_w2[(t * FIN + j) * FIN + l];
    const float b2 = pre_b2[t * FIN + l];

    {
        float w1c[FIN];
#pragma unroll
        for (int f = 0; f < FIN; f++) w1c[f] = pre_w1[(t * 96 + 64 + f) * FIN + l];
#pragma unroll
        for (int b = 0; b < 5; b++) {
            float et = g_enc[b * FIN + l];
            float a = 0.f;
#pragma unroll
            for (int f = 0; f < FIN; f++) a += __shfl_sync(FULLM, et, f) * w1c[f];
            evtab[t][b][l] = a;
        }
        __syncwarp();
    }
    const float* evs = &evtab[t][0][0];
    const int off = t * FIN + l;
    const int half = (N + 1) >> 1;

    for (int n = blockIdx.x; n < half; n += gridDim.x) {
        const int nA = n, nB = n + half;
        const bool hasB = nB < N;
        float a0A = g_a0[nA * H + off];
        int e0A = g_off[nA], e1A = g_off[nA + 1];
        float a0B = 0.f; int e0B = 0, e1B = 0;
        if (hasB) { a0B = g_a0[nB * H + off]; e0B = g_off[nB]; e1B = g_off[nB + 1]; }
        const int cntA = e1A - e0A, cntB = e1B - e0B;
        const int pAcnt = cntA >> 1, pBcnt = cntB >> 1;
        const int np = max(pAcnt, pBcnt);

        float sA = 0.f, qA = 0.f, sB = 0.f, qB = 0.f;
        float minA = FLT_MAX, maxA = -FLT_MAX, minB = FLT_MAX, maxB = -FLT_MAX;

        float paA = 0.f, pbA = 0.f, paB = 0.f, pbB = 0.f;
        float evaA = 0.f, evbA = 0.f, evaB = 0.f, evbB = 0.f;
        if (pAcnt > 0) {
            int k0 = g_csr[e0A], k1 = g_csr[e0A + 1];
            evaA = evs[(k0 >> 27) * 32 + l];
            evbA = evs[(k1 >> 27) * 32 + l];
            paA = g_p[(k0 & 0x07ffffff) + off];
            pbA = g_p[(k1 & 0x07ffffff) + off];
        }
        if (pBcnt > 0) {
            int k0 = g_csr[e0B], k1 = g_csr[e0B + 1];
            evaB = evs[(k0 >> 27) * 32 + l];
            evbB = evs[(k1 >> 27) * 32 + l];
            paB = g_p[(k0 & 0x07ffffff) + off];
            pbB = g_p[(k1 & 0x07ffffff) + off];
        }

        for (int i = 0; i < np; i++) {
            const int par = i & 1;
            const bool dA = i < pAcnt, dB = i < pBcnt;
            if (dA) {
                rs2[t][par][0][l] = make_float2(fmaxf(a0A + evaA + paA, 0.f),
                                                fmaxf(a0A + evbA + pbA, 0.f));
            }
            if (dB) {
                rs2[t][par][1][l] = make_float2(fmaxf(a0B + evaB + paB, 0.f),
                                                fmaxf(a0B + evbB + pbB, 0.f));
            }
            if (i + 1 < pAcnt) {
                int idx = e0A + 2 * (i + 1);
                int k0 = g_csr[idx], k1 = g_csr[idx + 1];
                evaA = evs[(k0 >> 27) * 32 + l];
                evbA = evs[(k1 >> 27) * 32 + l];
                paA = g_p[(k0 & 0x07ffffff) + off];
                pbA = g_p[(k1 & 0x07ffffff) + off];
            }
            if (i + 1 < pBcnt) {
                int idx = e0B + 2 * (i + 1);
                int k0 = g_csr[idx], k1 = g_csr[idx + 1];
                evaB = evs[(k0 >> 27) * 32 + l];
                evbB = evs[(k1 >> 27) * 32 + l];
                paB = g_p[(k0 & 0x07ffffff) + off];
                pbB = g_p[(k1 & 0x07ffffff) + off];
            }
            __syncwarp();
            if (dA) {
                float m0, m1;
                dot_pair(rs2[t][par][0], w2v, b2, m0, m1);
                sA += m0 + m1;
                qA = fmaf(m0, m0, qA); qA = fmaf(m1, m1, qA);
                minA = fminf(minA, fminf(m0, m1));
                maxA = fmaxf(maxA, fmaxf(m0, m1));
            }
            if (dB) {
                float m0, m1;
                dot_pair(rs2[t][par][1], w2v, b2, m0, m1);
                sB += m0 + m1;
                qB = fmaf(m0, m0, qB); qB = fmaf(m1, m1, qB);
                minB = fminf(minB, fminf(m0, m1));
                maxB = fmaxf(maxB, fmaxf(m0, m1));
            }
        }

        const bool tA = (cntA & 1) != 0, tB = (cntB & 1) != 0;
        if (tA | tB) {
            const int par = np & 1;
            if (tA) {
                int k = g_csr[e1A - 1];
                float p = g_p[(k & 0x07ffffff) + off];
                rs2[t][par][0][l] = make_float2(fmaxf(a0A + evs[(k >> 27) * 32 + l] + p, 0.f), 0.f);
            }
            if (tB) {
                int k = g_csr[e1B - 1];
                float p = g_p[(k & 0x07ffffff) + off];
                rs2[t][par][1][l] = make_float2(fmaxf(a0B + evs[(k >> 27) * 32 + l] + p, 0.f), 0.f);
            }
            __syncwarp();
            if (tA) {
                float m0, m1;
                dot_pair(rs2[t][par][0], w2v, b2, m0, m1);
                sA += m0; qA = fmaf(m0, m0, qA);
                minA = fminf(minA, m0); maxA = fmaxf(maxA, m0);
            }
            if (tB) {
                float m0, m1;
                dot_pair(rs2[t][par][1], w2v, b2, m0, m1);
                sB += m0; qB = fmaf(m0, m0, qB);
                minB = fminf(minB, m0); maxB = fmaxf(maxB, m0);
            }
        }

        {
            float c1 = fmaxf((float)cntA, 1.f);
            float mean = sA / c1;
            float stdv = sqrtf(fmaxf(qA / c1 - mean * mean, 0.f) + 1e-5f);
            float mn = minA, mx = maxA;
            if (cntA == 0) { mn = 0.f; mx = 0.f; }
            float* o = g_agg + (size_t)(nA * T + t) * 5 * FIN + l;
            o[0 * FIN] = sA; o[1 * FIN] = mean; o[2 * FIN] = mn;
            o[3 * FIN] = mx; o[4 * FIN] = stdv;
        }
        if (hasB) {
            float c1 = fmaxf((float)cntB, 1.f);
            float mean = sB / c1;
            float stdv = sqrtf(fmaxf(qB / c1 - mean * mean, 0.f) + 1e-5f);
            float mn = minB, mx = maxB;
            if (cntB == 0) { mn = 0.f; mx = 0.f; }
            float* o = g_agg + (size_t)(nB * T + t) * 5 * FIN + l;
            o[0 * FIN] = sB; o[1 * FIN] = mean; o[2 * FIN] = mn;
            o[3 * FIN] = mx; o[4 * FIN] = stdv;
        }
    }
}

// ---------------- fused tail: post-MLP (all 4 towers) + final linear + LayerNorm ----------------
// ISOLATED CHANGE: __launch_bounds__(128, 5) — smem 40KB x5 = 200KB fits; tests whether
// regs can reach 102 without spilling (R13 confound resolution).
__global__ void __launch_bounds__(128, 5) k_tail(
    const float* __restrict__ atom_x,
    const float* __restrict__ post_w1, const float* __restrict__ post_b1,
    const float* __restrict__ post_w2, const float* __restrict__ post_b2,
    const float* __restrict__ lin_w, const float* __restrict__ lin_b,
    const float* __restrict__ ln_g, const float* __restrict__ ln_b,
    float* __restrict__ out, int N) {
    const int w = threadIdx.x >> 5;
    const int g = threadIdx.x & 31;
    __shared__ __align__(16) float st[16][512];     // 32 KB, re-staged per tower
    __shared__ float red[4][16][32];                // 8 KB
    __shared__ float s1s[16], s2s[16];

    const int n0 = blockIdx.x * 16;

    if (threadIdx.x < 16) {
        int n = min(n0 + threadIdx.x, N - 1);
        float avg = g_avg_log;
        float c1 = fmaxf((float)g_deg[n], 1.f);
        float logd = logf(c1 + 1.f);
        s1s[threadIdx.x] = logd / avg;
        s2s[threadIdx.x] = avg / logd;
    }
    ull facc[4][2];
#pragma unroll
    for (int j2 = 0; j2 < 4; j2++) { facc[j2][0] = 0ull; facc[j2][1] = 0ull; }
    __syncthreads();

    for (int t = 0; t < T; t++) {
#pragma unroll
        for (int j2 = 0; j2 < 4; j2++) {
            const int j = w * 4 + j2;
            const int n = min(n0 + j, N - 1);
            float s1 = s1s[j], s2 = s2s[j];
            st[j][g] = atom_x[n * H + t * FIN + g];
            const float* ag = g_agg + (size_t)(n * T + t) * 5 * FIN;
#pragma unroll
            for (int a = 0; a < 5; a++) {
                float v = ag[a * FIN + g];
                st[j][32 + a * FIN + g] = v;
                st[j][192 + a * FIN + g] = v * s1;
                st[j][352 + a * FIN + g] = v * s2;
            }
        }
        __syncthreads();

        const float* wbase = post_w1 + (size_t)t * 512 * FIN + (size_t)(w * 128) * FIN + g;
        const int fbase = w * 128;
        ull acc[16];
#pragma unroll
        for (int nd = 0; nd < 16; nd++) acc[nd] = 0ull;
#pragma unroll 4
        for (int fq = 0; fq < 32; fq++) {
            const int f = fbase + 4 * fq;
            float wv0 = wbase[(4 * fq + 0) * FIN];
            float wv1 = wbase[(4 * fq + 1) * FIN];
            float wv2 = wbase[(4 * fq + 2) * FIN];
            float wv3 = wbase[(4 * fq + 3) * FIN];
            ull wd0 = packf2(wv0, wv1);
            ull wd1 = packf2(wv2, wv3);
#pragma unroll
            for (int nd = 0; nd < 16; nd++) {
                ulonglong2 v = *(const ulonglong2*)&st[nd][f];
                acc[nd] = fma2(v.x, wd0, acc[nd]);
                acc[nd] = fma2(v.y, wd1, acc[nd]);
            }
        }
#pragma unroll
        for (int nd = 0; nd < 16; nd++) {
            float lo, hi; unpackf2(acc[nd], lo, hi);
            red[w][nd][g] = lo + hi;
        }
        __syncthreads();

        const float b1 = post_b1[t * FIN + g];
        const float b2v = post_b2[t * FIN + g];
        const int j = w * 4;
        float m0 = fmaxf(red[0][j+0][g] + red[1][j+0][g] + red[2][j+0][g] + red[3][j+0][g] + b1, 0.f);
        float m1 = fmaxf(red[0][j+1][g] + red[1][j+1][g] + red[2][j+1][g] + red[3][j+1][g] + b1, 0.f);
        float m2 = fmaxf(red[0][j+2][g] + red[1][j+2][g] + red[2][j+2][g] + red[3][j+2][g] + b1, 0.f);
        float m3 = fmaxf(red[0][j+3][g] + red[1][j+3][g] + red[2][j+3][g] + red[3][j+3][g] + b1, 0.f);
        float o0 = b2v, o1 = b2v, o2 = b2v, o3 = b2v;
#pragma unroll
        for (int f = 0; f < FIN; f++) {
            float wv = __ldg(&post_w2[(t * FIN + f) * FIN + g]);
            o0 += __shfl_sync(FULLM, m0, f) * wv;
            o1 += __shfl_sync(FULLM, m1, f) * wv;
            o2 += __shfl_sync(FULLM, m2, f) * wv;
            o3 += __shfl_sync(FULLM, m3, f) * wv;
        }
#pragma unroll
        for (int f = 0; f < FIN; f++) {
            const float* lw = lin_w + (size_t)(t * FIN + f) * H + g;
            ull wda = packf2(__ldg(&lw[0]),  __ldg(&lw[32]));
            ull wdb = packf2(__ldg(&lw[64]), __ldg(&lw[96]));
            float y0 = __shfl_sync(FULLM, o0, f);
            float y1 = __shfl_sync(FULLM, o1, f);
            float y2 = __shfl_sync(FULLM, o2, f);
            float y3 = __shfl_sync(FULLM, o3, f);
            ull yd0 = packf2(y0, y0), yd1 = packf2(y1, y1);
            ull yd2 = packf2(y2, y2), yd3 = packf2(y3, y3);
            facc[0][0] = fma2(yd0, wda, facc[0][0]); facc[0][1] = fma2(yd0, wdb, facc[0][1]);
            facc[1][0] = fma2(yd1, wda, facc[1][0]); facc[1][1] = fma2(yd1, wdb, facc[1][1]);
            facc[2][0] = fma2(yd2, wda, facc[2][0]); facc[2][1] = fma2(yd2, wdb, facc[2][1]);
            facc[3][0] = fma2(yd3, wda, facc[3][0]); facc[3][1] = fma2(yd3, wdb, facc[3][1]);
        }
        __syncthreads();
    }

    const float lb0 = lin_b[g],      lb1 = lin_b[32 + g];
    const float lb2 = lin_b[64 + g], lb3 = lin_b[96 + g];
    const float ga0 = ln_g[g],      ga1 = ln_g[32 + g];
    const float ga2 = ln_g[64 + g], ga3 = ln_g[96 + g];
    const float be0 = ln_b[g],      be1 = ln_b[32 + g];
    const float be2 = ln_b[64 + g], be3 = ln_b[96 + g];

#pragma unroll
    for (int j2 = 0; j2 < 4; j2++) {
        int n = n0 + w * 4 + j2;
        float a0, a1, a2, a3;
        unpackf2(facc[j2][0], a0, a1);
        unpackf2(facc[j2][1], a2, a3);
        a0 += lb0; a1 += lb1; a2 += lb2; a3 += lb3;
        float s = a0 + a1 + a2 + a3;
        float q = a0 * a0 + a1 * a1 + a2 * a2 + a3 * a3;
#pragma unroll
        for (int off = 16; off > 0; off >>= 1) {
            s += __shfl_xor_sync(FULLM, s, off);
            q += __shfl_xor_sync(FULLM, q, off);
        }
        if (n < N) {
            float mu = s * (1.f / 128.f);
            float var = q * (1.f / 128.f) - mu * mu;
            float rstd = rsqrtf(var + 1e-5f);
            const float* ax = atom_x + (size_t)n * H;
            float* op = out + (size_t)n * H;
            op[g]      = ax[g]      + fmaxf((a0 - mu) * rstd * ga0 + be0, 0.f);
            op[32 + g] = ax[32 + g] + fmaxf((a1 - mu) * rstd * ga1 + be1, 0.f);
            op[64 + g] = ax[64 + g] + fmaxf((a2 - mu) * rstd * ga2 + be2, 0.f);
            op[96 + g] = ax[96 + g] + fmaxf((a3 - mu) * rstd * ga3 + be3, 0.f);
        }
    }
}

// ---------------- launch ----------------
extern "C" void kernel_launch(void* const* d_in, const int* in_sizes, int n_in,
                              void* d_out, int out_size) {
    const float* atom_x  = (const float*)d_in[0];
    const int*   bond_x  = (const int*)d_in[1];
    const int*   edge_ix = (const int*)d_in[2];
    const int*   mol_deg = (const int*)d_in[3];
    const float* bond_emb = (const float*)d_in[4];
    const float* enc_w   = (const float*)d_in[5];
    const float* enc_b   = (const float*)d_in[6];
    const float* pre_w1  = (const float*)d_in[7];
    const float* pre_b1  = (const float*)d_in[8];
    const float* pre_w2  = (const float*)d_in[9];
    const float* pre_b2  = (const float*)d_in[10];
    const float* post_w1 = (const float*)d_in[11];
    const float* post_b1 = (const float*)d_in[12];
    const float* post_w2 = (const float*)d_in[13];
    const float* post_b2 = (const float*)d_in[14];
    const float* lin_w   = (const float*)d_in[15];
    const float* lin_b   = (const float*)d_in[16];
    const float* ln_g    = (const float*)d_in[17];
    const float* ln_b    = (const float*)d_in[18];
    float* out = (float*)d_out;

    int N = in_sizes[0] / H;
    int E = in_sizes[1];
    const int* src = edge_ix;
    const int* dst = edge_ix + E;

    k_setup<<<NB, STH>>>(dst, src, bond_x, atom_x, pre_w1, pre_b1,
                         mol_deg, bond_emb, enc_w, enc_b, N, E);            // 0
    k_agg<<<888, 128>>>(pre_w1, pre_w2, pre_b2, N);                         // 1
    k_dummy<<<1, 32>>>();                                                   // 2 (shift ncu slot)
    k_tail<<<(N + 15) / 16, 128>>>(atom_x, post_w1, post_b1, post_w2, post_b2,
                                   lin_w, lin_b, ln_g, ln_b, out, N);       // 3 <- ncu target
}

// round 17
// speedup vs baseline: 1.0320x; 1.0320x over previous
#include <cuda_runtime.h>
#include <math.h>
#include <float.h>

#define NMAX 20000
#define EMAX 320000
#define H 128
#define T 4
#define FIN 32
#define FULLM 0xffffffffu
#define NB 132     // resident blocks for fused setup
#define STH 512    // k_setup threads per block

typedef unsigned long long ull;

// ---------------- f32x2 packed helpers ----------------
__device__ __forceinline__ ull packf2(float lo, float hi) {
    ull r;
    asm("mov.b64 %0, {%1, %2};" : "=l"(r) : "r"(__float_as_uint(lo)), "r"(__float_as_uint(hi)));
    return r;
}
__device__ __forceinline__ void unpackf2(ull v, float& lo, float& hi) {
    unsigned int a, b;
    asm("mov.b64 {%0, %1}, %2;" : "=r"(a), "=r"(b) : "l"(v));
    lo = __uint_as_float(a); hi = __uint_as_float(b);
}
__device__ __forceinline__ ull fma2(ull a, ull b, ull c) {
    ull d;
    asm("fma.rn.f32x2 %0, %1, %2, %3;" : "=l"(d) : "l"(a), "l"(b), "l"(c));
    return d;
}
__device__ __forceinline__ ull add2(ull a, ull b) {
    ull d;
    asm("add.rn.f32x2 %0, %1, %2;" : "=l"(d) : "l"(a), "l"(b));
    return d;
}

// ---------------- device scratch ----------------
__device__ float g_avg_log;
__device__ float g_enc[5 * FIN];
__device__ int   g_deg[NMAX];
__device__ int   g_off[NMAX + 1];
__device__ int   g_fill[NMAX];
__device__ int   g_csr[EMAX];                 // packed: (src*H) | (bond<<27)
__device__ int   g_part[NB];
__device__ float g_a0[(size_t)NMAX * H];
__device__ float g_p [(size_t)NMAX * H];
__device__ float g_agg[(size_t)NMAX * T * 5 * FIN];
__device__ unsigned int g_bar;
__device__ unsigned int g_done;

// ---------------- fused setup: zero + hist + PRE + SCALARS + scan + scatter ----------------
__device__ __forceinline__ void grid_bar(unsigned target) {
    __syncthreads();
    if (threadIdx.x == 0) {
        __threadfence();
        atomicAdd(&g_bar, 1u);
        while (*((volatile unsigned int*)&g_bar) < target) { }
        __threadfence();
    }
    __syncthreads();
}

__global__ void __launch_bounds__(STH) k_setup(
    const int* __restrict__ dst, const int* __restrict__ src,
    const int* __restrict__ bond,
    const float* __restrict__ atom_x,
    const float* __restrict__ pre_w1, const float* __restrict__ pre_b1,
    const int* __restrict__ mol_deg,
    const float* __restrict__ bond_emb,
    const float* __restrict__ enc_w, const float* __restrict__ enc_b,
    int N, int E) {
    const int tid = threadIdx.x, b = blockIdx.x;
    const int gsz = NB * STH;
    const int gid = b * STH + tid;
    __shared__ int sh[STH];
    __shared__ float sf[256], sf2[256];
    __shared__ int s_poff;

    // P0: zero degree counters
    for (int i = gid; i < N; i += gsz) __stcg(&g_deg[i], 0);
    grid_bar(NB * 1);

    // P1: degree histogram
    for (int e = gid; e < E; e += gsz) atomicAdd(&g_deg[__ldg(&dst[e])], 1);

    // SCALARS (block 1, independent of hist): avg_log + bond-encode table
    if (b == 1 && tid < 256) {
        float num = 0.f, den = 0.f;
        if (tid < 128) {
            float d = (float)mol_deg[tid];
            num = logf((float)tid + 1.0f) * d;
            den = d;
        }
        sf[tid] = num; sf2[tid] = den;
        __syncwarp();
    }
    if (b == 1) {
        __syncthreads();
        if (tid < 128) { sf[tid] += sf[tid + 128]; sf2[tid] += sf2[tid + 128]; }
        __syncthreads();
        if (tid < 64) { sf[tid] += sf[tid + 64]; sf2[tid] += sf2[tid + 64]; }
        __syncthreads();
        if (tid < 32) {
            float s = sf[tid] + sf[tid + 32];
            float d = sf2[tid] + sf2[tid + 32];
#pragma unroll
            for (int off = 16; off > 0; off >>= 1) {
                s += __shfl_down_sync(FULLM, s, off);
                d += __shfl_down_sync(FULLM, d, off);
            }
            if (tid == 0) g_avg_log = s / d;
        }
        if (tid < 5 * FIN) {
            int bb = tid >> 5, g = tid & 31;
            float a = enc_b[g];
            for (int k = 0; k < H; k++) a += bond_emb[bb * H + k] * enc_w[k * FIN + g];
            g_enc[bb * FIN + g] = a;
        }
        __syncthreads();
    }

    // PRE (independent of hist): A0 = b1 + W1a.x, P = W1b.x
    {
        const int l = tid & 31;
        const int w = tid >> 5;
        const int t = w & 3;
        float w1a[FIN], w1b[FIN];
#pragma unroll
        for (int f = 0; f < FIN; f++) w1a[f] = pre_w1[(t * 96 + f) * FIN + l];
#pragma unroll
        for (int f = 0; f < FIN; f++) w1b[f] = pre_w1[(t * 96 + 32 + f) * FIN + l];
        const float b1 = pre_b1[t * FIN + l];
        for (int n = b * 8 + (w >> 2) * 2; n < N; n += NB * 8) {
            const bool has2 = (n + 1) < N;
            const int n2 = has2 ? n + 1 : n;
            float x0 = atom_x[n * H + t * FIN + l];
            float x1 = atom_x[n2 * H + t * FIN + l];
            float a00 = b1, p0 = 0.f, a01 = b1, p1 = 0.f;
#pragma unroll
            for (int f = 0; f < FIN; f++) {
                float xf0 = __shfl_sync(FULLM, x0, f);
                float xf1 = __shfl_sync(FULLM, x1, f);
                a00 += xf0 * w1a[f];
                p0  += xf0 * w1b[f];
                a01 += xf1 * w1a[f];
                p1  += xf1 * w1b[f];
            }
            g_a0[n * H + t * FIN + l] = a00;
            g_p [n * H + t * FIN + l] = p0;
            if (has2) {
                g_a0[n2 * H + t * FIN + l] = a01;
                g_p [n2 * H + t * FIN + l] = p1;
            }
        }
    }
    grid_bar(NB * 2);

    // P2: per-block chunk scan
    const int chunk = (N + NB - 1) / NB;
    const int i = b * chunk + tid;
    int v = (tid < chunk && i < N) ? __ldcg(&g_deg[i]) : 0;
    sh[tid] = v;
    __syncthreads();
    for (int off = 1; off < STH; off <<= 1) {
        int tv = (tid >= off) ? sh[tid - off] : 0;
        __syncthreads();
        sh[tid] += tv;
        __syncthreads();
    }
    int local_excl = sh[tid] - v;
    if (tid == STH - 1) __stcg(&g_part[b], sh[STH - 1]);
    grid_bar(NB * 3);

    // P3: every block computes its own prefix over g_part[<b]
    if (tid < 32) {
        int s = 0;
        for (int ii = tid; ii < b; ii += 32) s += __ldcg(&g_part[ii]);
#pragma unroll
        for (int off = 16; off > 0; off >>= 1) s += __shfl_down_sync(FULLM, s, off);
        if (tid == 0) s_poff = s;
    }
    if (b == 0 && tid == 33) __stcg(&g_off[N], E);
    __syncthreads();
    {
        int po = s_poff;
        if (tid < chunk && i < N) {
            int vv = local_excl + po;
            __stcg(&g_off[i], vv);
            __stcg(&g_fill[i], vv);
        }
    }
    grid_bar(NB * 4);

    // P5: scatter edges into CSR (src pre-multiplied by H)
    for (int e = gid; e < E; e += gsz) {
        int d = __ldg(&dst[e]);
        int p = atomicAdd(&g_fill[d], 1);
        __stcg(&g_csr[p], (__ldg(&src[e]) * H) | (__ldg(&bond[e]) << 27));
    }

    __syncthreads();
    if (tid == 0) {
        if (atomicAdd(&g_done, 1u) == NB - 1) {
            atomicExch(&g_bar, 0u);
            atomicExch(&g_done, 0u);
        }
    }
}

// ---------------- edge loop: dual-node, edge-major staging, smem ev table ----------------
// single-chain dot (best-measured configuration)
__device__ __forceinline__ float dot_edge(const float* buf, const ull* w2d, float b2) {
    ull acc = 0ull;
#pragma unroll
    for (int j = 0; j < 8; j++) {
        ulonglong2 v = *(const ulonglong2*)&buf[4 * j];
        acc = fma2(v.x, w2d[2 * j], acc);
        acc = fma2(v.y, w2d[2 * j + 1], acc);
    }
    float lo, hi; unpackf2(acc, lo, hi);
    return lo + hi + b2;
}

__global__ void __launch_bounds__(128, 6) k_agg(
    const float* __restrict__ pre_w1,
    const float* __restrict__ pre_w2, const float* __restrict__ pre_b2, int N) {
    const int l = threadIdx.x & 31;
    const int t = threadIdx.x >> 5;
    __shared__ __align__(16) float rs[4][2][4][32];   // [warp][parity][edge-slot][feature]
    __shared__ float evtab[4][5][32];                 // [warp][bond][lane]

    ull w2d[16];
#pragma unroll
    for (int j = 0; j < 16; j++)
        w2d[j] = packf2(pre_w2[(t * FIN + 2 * j) * FIN + l],
                        pre_w2[(t * FIN + 2 * j + 1) * FIN + l]);
    const float b2 = pre_b2[t * FIN + l];

    {
        float w1c[FIN];
#pragma unroll
        for (int f = 0; f < FIN; f++) w1c[f] = pre_w1[(t * 96 + 64 + f) * FIN + l];
#pragma unroll
        for (int b = 0; b < 5; b++) {
            float et = g_enc[b * FIN + l];
            float a = 0.f;
#pragma unroll
            for (int f = 0; f < FIN; f++) a += __shfl_sync(FULLM, et, f) * w1c[f];
            evtab[t][b][l] = a;
        }
        __syncwarp();
    }
    const float* evs = &evtab[t][0][0];
    const int off = t * FIN + l;
    const int half = (N + 1) >> 1;

    for (int n = blockIdx.x; n < half; n += gridDim.x) {
        const int nA = n, nB = n + half;
        const bool hasB = nB < N;
        float a0A = g_a0[nA * H + off];
        int e0A = g_off[nA], e1A = g_off[nA + 1];
        float a0B = 0.f; int e0B = 0, e1B = 0;
        if (hasB) { a0B = g_a0[nB * H + off]; e0B = g_off[nB]; e1B = g_off[nB + 1]; }
        const int cntA = e1A - e0A, cntB = e1B - e0B;
        const int pAcnt = cntA >> 1, pBcnt = cntB >> 1;
        const int np = max(pAcnt, pBcnt);

        float sA = 0.f, qA = 0.f, sB = 0.f, qB = 0.f;
        float minA = FLT_MAX, maxA = -FLT_MAX, minB = FLT_MAX, maxB = -FLT_MAX;

        float paA = 0.f, pbA = 0.f, paB = 0.f, pbB = 0.f;
        float evaA = 0.f, evbA = 0.f, evaB = 0.f, evbB = 0.f;
        if (pAcnt > 0) {
            int k0 = g_csr[e0A], k1 = g_csr[e0A + 1];
            evaA = evs[(k0 >> 27) * 32 + l];
            evbA = evs[(k1 >> 27) * 32 + l];
            paA = g_p[(k0 & 0x07ffffff) + off];
            pbA = g_p[(k1 & 0x07ffffff) + off];
        }
        if (pBcnt > 0) {
            int k0 = g_csr[e0B], k1 = g_csr[e0B + 1];
            evaB = evs[(k0 >> 27) * 32 + l];
            evbB = evs[(k1 >> 27) * 32 + l];
            paB = g_p[(k0 & 0x07ffffff) + off];
            pbB = g_p[(k1 & 0x07ffffff) + off];
        }

        for (int i = 0; i < np; i++) {
            const int par = i & 1;
            const bool dA = i < pAcnt, dB = i < pBcnt;
            if (dA) {
                rs[t][par][0][l] = fmaxf(a0A + evaA + paA, 0.f);
                rs[t][par][1][l] = fmaxf(a0A + evbA + pbA, 0.f);
            }
            if (dB) {
                rs[t][par][2][l] = fmaxf(a0B + evaB + paB, 0.f);
                rs[t][par][3][l] = fmaxf(a0B + evbB + pbB, 0.f);
            }
            if (i + 1 < pAcnt) {
                int idx = e0A + 2 * (i + 1);
                int k0 = g_csr[idx], k1 = g_csr[idx + 1];
                evaA = evs[(k0 >> 27) * 32 + l];
                evbA = evs[(k1 >> 27) * 32 + l];
                paA = g_p[(k0 & 0x07ffffff) + off];
                pbA = g_p[(k1 & 0x07ffffff) + off];
            }
            if (i + 1 < pBcnt) {
                int idx = e0B + 2 * (i + 1);
                int k0 = g_csr[idx], k1 = g_csr[idx + 1];
                evaB = evs[(k0 >> 27) * 32 + l];
                evbB = evs[(k1 >> 27) * 32 + l];
                paB = g_p[(k0 & 0x07ffffff) + off];
                pbB = g_p[(k1 & 0x07ffffff) + off];
            }
            __syncwarp();
            if (dA) {
                float m0 = dot_edge(rs[t][par][0], w2d, b2);
                float m1 = dot_edge(rs[t][par][1], w2d, b2);
                sA += m0 + m1;
                qA = fmaf(m0, m0, qA); qA = fmaf(m1, m1, qA);
                minA = fminf(minA, fminf(m0, m1));
                maxA = fmaxf(maxA, fmaxf(m0, m1));
            }
            if (dB) {
                float m0 = dot_edge(rs[t][par][2], w2d, b2);
                float m1 = dot_edge(rs[t][par][3], w2d, b2);
                sB += m0 + m1;
                qB = fmaf(m0, m0, qB); qB = fmaf(m1, m1, qB);
                minB = fminf(minB, fminf(m0, m1));
                maxB = fmaxf(maxB, fmaxf(m0, m1));
            }
        }

        const bool tA = (cntA & 1) != 0, tB = (cntB & 1) != 0;
        if (tA | tB) {
            const int par = np & 1;
            if (tA) {
                int k = g_csr[e1A - 1];
                float p = g_p[(k & 0x07ffffff) + off];
                rs[t][par][0][l] = fmaxf(a0A + evs[(k >> 27) * 32 + l] + p, 0.f);
            }
            if (tB) {
                int k = g_csr[e1B - 1];
                float p = g_p[(k & 0x07ffffff) + off];
                rs[t][par][2][l] = fmaxf(a0B + evs[(k >> 27) * 32 + l] + p, 0.f);
            }
            __syncwarp();
            if (tA) {
                float m0 = dot_edge(rs[t][par][0], w2d, b2);
                sA += m0; qA = fmaf(m0, m0, qA);
                minA = fminf(minA, m0); maxA = fmaxf(maxA, m0);
            }
            if (tB) {
                float m0 = dot_edge(rs[t][par][2], w2d, b2);
                sB += m0; qB = fmaf(m0, m0, qB);
                minB = fminf(minB, m0); maxB = fmaxf(maxB, m0);
            }
        }

        {
            float c1 = fmaxf((float)cntA, 1.f);
            float mean = sA / c1;
            float stdv = sqrtf(fmaxf(qA / c1 - mean * mean, 0.f) + 1e-5f);
            float mn = minA, mx = maxA;
            if (cntA == 0) { mn = 0.f; mx = 0.f; }
            float* o = g_agg + (size_t)(nA * T + t) * 5 * FIN + l;
            o[0 * FIN] = sA; o[1 * FIN] = mean; o[2 * FIN] = mn;
            o[3 * FIN] = mx; o[4 * FIN] = stdv;
        }
        if (hasB) {
            float c1 = fmaxf((float)cntB, 1.f);
            float mean = sB / c1;
            float stdv = sqrtf(fmaxf(qB / c1 - mean * mean, 0.f) + 1e-5f);
            float mn = minB, mx = maxB;
            if (cntB == 0) { mn = 0.f; mx = 0.f; }
            float* o = g_agg + (size_t)(nB * T + t) * 5 * FIN + l;
            o[0 * FIN] = sB; o[1 * FIN] = mean; o[2 * FIN] = mn;
            o[3 * FIN] = mx; o[4 * FIN] = stdv;
        }
    }
}

// ---------------- fused tail: post-MLP (all 4 towers) + final linear + LayerNorm ----------------
__global__ void __launch_bounds__(128, 4) k_tail(
    const float* __restrict__ atom_x,
    const float* __restrict__ post_w1, const float* __restrict__ post_b1,
    const float* __restrict__ post_w2, const float* __restrict__ post_b2,
    const float* __restrict__ lin_w, const float* __restrict__ lin_b,
    const float* __restrict__ ln_g, const float* __restrict__ ln_b,
    float* __restrict__ out, int N) {
    const int w = threadIdx.x >> 5;
    const int g = threadIdx.x & 31;
    __shared__ __align__(16) float st[16][512];     // 32 KB, re-staged per tower
    __shared__ float red[4][16][32];                // 8 KB
    __shared__ float s1s[16], s2s[16];

    const int n0 = blockIdx.x * 16;

    if (threadIdx.x < 16) {
        int n = min(n0 + threadIdx.x, N - 1);
        float avg = g_avg_log;
        float c1 = fmaxf((float)g_deg[n], 1.f);
        float logd = logf(c1 + 1.f);
        s1s[threadIdx.x] = logd / avg;
        s2s[threadIdx.x] = avg / logd;
    }
    ull facc[4][2];
#pragma unroll
    for (int j2 = 0; j2 < 4; j2++) { facc[j2][0] = 0ull; facc[j2][1] = 0ull; }
    __syncthreads();

    for (int t = 0; t < T; t++) {
#pragma unroll
        for (int j2 = 0; j2 < 4; j2++) {
            const int j = w * 4 + j2;
            const int n = min(n0 + j, N - 1);
            float s1 = s1s[j], s2 = s2s[j];
            st[j][g] = atom_x[n * H + t * FIN + g];
            const float* ag = g_agg + (size_t)(n * T + t) * 5 * FIN;
#pragma unroll
            for (int a = 0; a < 5; a++) {
                float v = ag[a * FIN + g];
                st[j][32 + a * FIN + g] = v;
                st[j][192 + a * FIN + g] = v * s1;
                st[j][352 + a * FIN + g] = v * s2;
            }
        }
        __syncthreads();

        const float* wbase = post_w1 + (size_t)t * 512 * FIN + (size_t)(w * 128) * FIN + g;
        const int fbase = w * 128;
        ull acc[16];
#pragma unroll
        for (int nd = 0; nd < 16; nd++) acc[nd] = 0ull;
#pragma unroll 4
        for (int fq = 0; fq < 32; fq++) {
            const int f = fbase + 4 * fq;
            float wv0 = wbase[(4 * fq + 0) * FIN];
            float wv1 = wbase[(4 * fq + 1) * FIN];
            float wv2 = wbase[(4 * fq + 2) * FIN];
            float wv3 = wbase[(4 * fq + 3) * FIN];
            ull wd0 = packf2(wv0, wv1);
            ull wd1 = packf2(wv2, wv3);
#pragma unroll
            for (int nd = 0; nd < 16; nd++) {
                ulonglong2 v = *(const ulonglong2*)&st[nd][f];
                acc[nd] = fma2(v.x, wd0, acc[nd]);
                acc[nd] = fma2(v.y, wd1, acc[nd]);
            }
        }
#pragma unroll
        for (int nd = 0; nd < 16; nd++) {
            float lo, hi; unpackf2(acc[nd], lo, hi);
            red[w][nd][g] = lo + hi;
        }
        __syncthreads();

        const float b1 = post_b1[t * FIN + g];
        const float b2v = post_b2[t * FIN + g];
        const int j = w * 4;
        float m0 = fmaxf(red[0][j+0][g] + red[1][j+0][g] + red[2][j+0][g] + red[3][j+0][g] + b1, 0.f);
        float m1 = fmaxf(red[0][j+1][g] + red[1][j+1][g] + red[2][j+1][g] + red[3][j+1][g] + b1, 0.f);
        float m2 = fmaxf(red[0][j+2][g] + red[1][j+2][g] + red[2][j+2][g] + red[3][j+2][g] + b1, 0.f);
        float m3 = fmaxf(red[0][j+3][g] + red[1][j+3][g] + red[2][j+3][g] + red[3][j+3][g] + b1, 0.f);
        float o0 = b2v, o1 = b2v, o2 = b2v, o3 = b2v;
#pragma unroll
        for (int f = 0; f < FIN; f++) {
            float wv = __ldg(&post_w2[(t * FIN + f) * FIN + g]);
            o0 += __shfl_sync(FULLM, m0, f) * wv;
            o1 += __shfl_sync(FULLM, m1, f) * wv;
            o2 += __shfl_sync(FULLM, m2, f) * wv;
            o3 += __shfl_sync(FULLM, m3, f) * wv;
        }
#pragma unroll
        for (int f = 0; f < FIN; f++) {
            const float* lw = lin_w + (size_t)(t * FIN + f) * H + g;
            ull wda = packf2(__ldg(&lw[0]),  __ldg(&lw[32]));
            ull wdb = packf2(__ldg(&lw[64]), __ldg(&lw[96]));
            float y0 = __shfl_sync(FULLM, o0, f);
            float y1 = __shfl_sync(FULLM, o1, f);
            float y2 = __shfl_sync(FULLM, o2, f);
            float y3 = __shfl_sync(FULLM, o3, f);
            ull yd0 = packf2(y0, y0), yd1 = packf2(y1, y1);
            ull yd2 = packf2(y2, y2), yd3 = packf2(y3, y3);
            facc[0][0] = fma2(yd0, wda, facc[0][0]); facc[0][1] = fma2(yd0, wdb, facc[0][1]);
            facc[1][0] = fma2(yd1, wda, facc[1][0]); facc[1][1] = fma2(yd1, wdb, facc[1][1]);
            facc[2][0] = fma2(yd2, wda, facc[2][0]); facc[2][1] = fma2(yd2, wdb, facc[2][1]);
            facc[3][0] = fma2(yd3, wda, facc[3][0]); facc[3][1] = fma2(yd3, wdb, facc[3][1]);
        }
        __syncthreads();
    }

    const float lb0 = lin_b[g],      lb1 = lin_b[32 + g];
    const float lb2 = lin_b[64 + g], lb3 = lin_b[96 + g];
    const float ga0 = ln_g[g],      ga1 = ln_g[32 + g];
    const float ga2 = ln_g[64 + g], ga3 = ln_g[96 + g];
    const float be0 = ln_b[g],      be1 = ln_b[32 + g];
    const float be2 = ln_b[64 + g], be3 = ln_b[96 + g];

#pragma unroll
    for (int j2 = 0; j2 < 4; j2++) {
        int n = n0 + w * 4 + j2;
        float a0, a1, a2, a3;
        unpackf2(facc[j2][0], a0, a1);
        unpackf2(facc[j2][1], a2, a3);
        a0 += lb0; a1 += lb1; a2 += lb2; a3 += lb3;
        float s = a0 + a1 + a2 + a3;
        float q = a0 * a0 + a1 * a1 + a2 * a2 + a3 * a3;
#pragma unroll
        for (int off = 16; off > 0; off >>= 1) {
            s += __shfl_xor_sync(FULLM, s, off);
            q += __shfl_xor_sync(FULLM, q, off);
        }
        if (n < N) {
            float mu = s * (1.f / 128.f);
            float var = q * (1.f / 128.f) - mu * mu;
            float rstd = rsqrtf(var + 1e-5f);
            const float* ax = atom_x + (size_t)n * H;
            float* op = out + (size_t)n * H;
            op[g]      = ax[g]      + fmaxf((a0 - mu) * rstd * ga0 + be0, 0.f);
            op[32 + g] = ax[32 + g] + fmaxf((a1 - mu) * rstd * ga1 + be1, 0.f);
            op[64 + g] = ax[64 + g] + fmaxf((a2 - mu) * rstd * ga2 + be2, 0.f);
            op[96 + g] = ax[96 + g] + fmaxf((a3 - mu) * rstd * ga3 + be3, 0.f);
        }
    }
}

// ---------------- launch ----------------
extern "C" void kernel_launch(void* const* d_in, const int* in_sizes, int n_in,
                              void* d_out, int out_size) {
    const float* atom_x  = (const float*)d_in[0];
    const int*   bond_x  = (const int*)d_in[1];
    const int*   edge_ix = (const int*)d_in[2];
    const int*   mol_deg = (const int*)d_in[3];
    const float* bond_emb = (const float*)d_in[4];
    const float* enc_w   = (const float*)d_in[5];
    const float* enc_b   = (const float*)d_in[6];
    const float* pre_w1  = (const float*)d_in[7];
    const float* pre_b1  = (const float*)d_in[8];
    const float* pre_w2  = (const float*)d_in[9];
    const float* pre_b2  = (const float*)d_in[10];
    const float* post_w1 = (const float*)d_in[11];
    const float* post_b1 = (const float*)d_in[12];
    const float* post_w2 = (const float*)d_in[13];
    const float* post_b2 = (const float*)d_in[14];
    const float* lin_w   = (const float*)d_in[15];
    const float* lin_b   = (const float*)d_in[16];
    const float* ln_g    = (const float*)d_in[17];
    const float* ln_b    = (const float*)d_in[18];
    float* out = (float*)d_out;

    int N = in_sizes[0] / H;
    int E = in_sizes[1];
    const int* src = edge_ix;
    const int* dst = edge_ix + E;

    k_setup<<<NB, STH>>>(dst, src, bond_x, atom_x, pre_w1, pre_b1,
                         mol_deg, bond_emb, enc_w, enc_b, N, E);            // 0
    k_agg<<<888, 128>>>(pre_w1, pre_w2, pre_b2, N);                         // 1
    k_tail<<<(N + 15) / 16, 128>>>(atom_x, post_w1, post_b1, post_w2, post_b2,
                                   lin_w, lin_b, ln_g, ln_b, out, N);       // 2
}